// round 1
// baseline (speedup 1.0000x reference)
#include <cuda_runtime.h>
#include <cstdint>

// ---------------------------------------------------------------------------
// FFT-based "mura" metric:
//   gray = mean_c(images)                          [32,512,512]
//   M    = |fft2(gray)|
//   score_b = sum(M * mask) / sum(M);   out = mean_b(score_b)
// mask: (u-256)^2 + (k-256)^2 <= (51.2)^2  (un-shifted FFT coords, as reference)
//
// Implementation: two-pass 512-pt FFT (rows then columns) with a transposed
// complex intermediate in a __device__ global. Each 512-pt FFT is a 3-pass
// radix-8 Cooley-Tukey done by 64 threads x 8 complex registers, with two
// shared-memory exchanges (natural-order output, no bit reversal anywhere).
// ---------------------------------------------------------------------------

#define PITCH 548            // float2 per per-row shared buffer (bank-friendly)
#define RPB   4              // rows per block
#define NTHR  256

__device__ float2 g_scratch[32u * 512u * 512u];   // transposed row-FFT output: [b][k][r]
__device__ float  g_plow[32 * 128];
__device__ float  g_ptot[32 * 128];

__device__ __forceinline__ float2 cadd(float2 a, float2 b){ return make_float2(a.x+b.x, a.y+b.y); }
__device__ __forceinline__ float2 csub(float2 a, float2 b){ return make_float2(a.x-b.x, a.y-b.y); }
__device__ __forceinline__ float2 cmul(float2 a, float2 b){
    return make_float2(a.x*b.x - a.y*b.y, a.x*b.y + a.y*b.x);
}
__device__ __forceinline__ float2 mnegi(float2 a){ return make_float2( a.y, -a.x); } // * (-i)
__device__ __forceinline__ float2 mposi(float2 a){ return make_float2(-a.y,  a.x); } // * (+i)

// 8-point DFT, natural output order: v[m'] = sum_m v_in[m] * w8^(m*m'),  w8 = e^{-i pi/4}
__device__ __forceinline__ void dft8(float2* v){
    const float C = 0.70710678118654752440f;
    // E = dft4(v0,v2,v4,v6)
    float2 t0 = cadd(v[0], v[4]);
    float2 t1 = csub(v[0], v[4]);
    float2 t2 = cadd(v[2], v[6]);
    float2 t3 = csub(v[2], v[6]);
    float2 E0 = cadd(t0, t2), E2 = csub(t0, t2);
    float2 E1 = cadd(t1, mnegi(t3));
    float2 E3 = cadd(t1, mposi(t3));
    // O = dft4(v1,v3,v5,v7)
    float2 s0 = cadd(v[1], v[5]);
    float2 s1 = csub(v[1], v[5]);
    float2 s2 = cadd(v[3], v[7]);
    float2 s3 = csub(v[3], v[7]);
    float2 O0 = cadd(s0, s2), O2 = csub(s0, s2);
    float2 O1 = cadd(s1, mnegi(s3));
    float2 O3 = cadd(s1, mposi(s3));
    // twiddled odd terms: w8^1 O1, w8^2 O2, w8^3 O3
    float2 w1O1 = make_float2(C*(O1.x + O1.y), C*(O1.y - O1.x));
    float2 w2O2 = mnegi(O2);
    float2 w3O3 = make_float2(C*(O3.y - O3.x), -C*(O3.x + O3.y));
    v[0] = cadd(E0, O0);   v[4] = csub(E0, O0);
    v[1] = cadd(E1, w1O1); v[5] = csub(E1, w1O1);
    v[2] = cadd(E2, w2O2); v[6] = csub(E2, w2O2);
    v[3] = cadd(E3, w3O3); v[7] = csub(E3, w3O3);
}

// Cooperative 512-pt FFT across the 64 threads sharing `srow` (thread index n in 0..63).
// Input : a[m] = x[n + 64*m]
// Output: a[t1] = X[(n>>3) + 8*(n&7) + 64*t1]   (natural frequency order)
// Contains __syncthreads(): all 256 threads of the block must call this together.
__device__ __forceinline__ void fft512(float2 a[8], float2* srow, const float2* tw, int n){
    int j = n;
    dft8(a);
    #pragma unroll
    for (int m = 1; m < 8; m++) a[m] = cmul(a[m], tw[(j * m) & 511]);
    #pragma unroll
    for (int m = 0; m < 8; m++) srow[m * 68 + j] = a[m];
    __syncthreads();

    int mp = n >> 3, i = n & 7;
    #pragma unroll
    for (int s = 0; s < 8; s++) a[s] = srow[mp * 68 + i + 8 * s];
    __syncthreads();

    dft8(a);
    #pragma unroll
    for (int t0 = 1; t0 < 8; t0++) a[t0] = cmul(a[t0], tw[(8 * i * t0) & 511]);
    #pragma unroll
    for (int t0 = 0; t0 < 8; t0++) srow[mp * 68 + 8 * t0 + i] = a[t0];
    __syncthreads();

    #pragma unroll
    for (int ii = 0; ii < 8; ii++) a[ii] = srow[mp * 68 + 8 * i + ii];
    dft8(a);
    // a[t1] = X[mp + 8*i + 64*t1]
}

__device__ __forceinline__ void build_tw(float2* tw, int tid){
    // tw[t] = e^{-2 pi i t / 512}, t = 0..511  (256 threads build 512 entries)
    float ang = (-6.283185307179586476925f / 512.0f) * (float)tid;
    float s, c;
    sincosf(ang, &s, &c);
    tw[tid]       = make_float2( c,  s);
    tw[tid + 256] = make_float2(-c, -s);
}

// Kernel 1: gray + row FFT, write transposed complex scratch  T[b][k][r]
__global__ void __launch_bounds__(NTHR) fft_rows_kernel(const float* __restrict__ img){
    __shared__ float2 sbuf[RPB * PITCH];
    __shared__ float2 tw[512];
    int tid = threadIdx.x;
    build_tw(tw, tid);
    __syncthreads();

    int b  = blockIdx.x >> 7;          // image
    int r0 = (blockIdx.x & 127) << 2;  // first of 4 rows
    int rr = tid >> 6;
    int n  = tid & 63;
    int row = r0 + rr;

    const float* p = img + (size_t)b * 786432u + (size_t)row * 512u;
    float2 a[8];
    #pragma unroll
    for (int m = 0; m < 8; m++){
        int c = n + 64 * m;
        float g = (p[c] + p[262144 + c] + p[524288 + c]) * (1.0f / 3.0f);
        a[m] = make_float2(g, 0.0f);
    }

    float2* srow = sbuf + rr * PITCH;
    fft512(a, srow, tw, n);
    __syncthreads();   // pass-3 loads complete before staging overwrites sbuf

    // stage natural-k results into shared (rotate t1 per lane -> 2-way max conflicts)
    int mp = n >> 3, i = n & 7;
    int kb = mp + 8 * i;
    #pragma unroll
    for (int t = 0; t < 8; t++){
        int t1 = (t + i) & 7;
        srow[kb + 64 * t1] = a[t1];
    }
    __syncthreads();

    // coalesced transposed write: T[b][k][r0..r0+3], 32B sectors fully used
    float2* dst = g_scratch + ((size_t)(b * 512) << 9);
    #pragma unroll
    for (int idx = tid; idx < 512 * RPB; idx += NTHR){
        int k  = idx >> 2;
        int r2 = idx & 3;
        dst[((size_t)k << 9) + (r0 + r2)] = sbuf[r2 * PITCH + k];
    }
}

// Kernel 2: column FFT per scratch row (= fixed k), magnitude + masked sums
__global__ void __launch_bounds__(NTHR) fft_cols_kernel(void){
    __shared__ float2 sbuf[RPB * PITCH];
    __shared__ float2 tw[512];
    __shared__ float redL[8], redT[8];
    int tid = threadIdx.x;
    build_tw(tw, tid);
    __syncthreads();

    int b  = blockIdx.x >> 7;
    int k0 = (blockIdx.x & 127) << 2;
    int rr = tid >> 6;
    int n  = tid & 63;
    int krow = k0 + rr;

    const float2* src = g_scratch + ((size_t)(b * 512 + krow) << 9);
    float2 a[8];
    #pragma unroll
    for (int m = 0; m < 8; m++) a[m] = src[n + 64 * m];

    fft512(a, sbuf + rr * PITCH, tw, n);

    // accumulate: a[t1] = F[u][krow], u = (n>>3) + 8*(n&7) + 64*t1 (natural)
    int mp = n >> 3, i = n & 7;
    int ub = mp + 8 * i;
    float dx  = (float)(krow - 256);
    float dx2 = dx * dx;
    float L = 0.0f, T = 0.0f;
    #pragma unroll
    for (int t1 = 0; t1 < 8; t1++){
        int u = ub + 64 * t1;
        float2 v = a[t1];
        float mag = sqrtf(v.x * v.x + v.y * v.y);
        T += mag;
        float dy = (float)(u - 256);
        if (dy * dy + dx2 <= 2621.44f) L += mag;   // (51.2)^2
    }

    // block reduction -> deterministic per-block partials
    #pragma unroll
    for (int o = 16; o; o >>= 1){
        L += __shfl_down_sync(0xffffffffu, L, o);
        T += __shfl_down_sync(0xffffffffu, T, o);
    }
    int wid = tid >> 5, lane = tid & 31;
    if (lane == 0){ redL[wid] = L; redT[wid] = T; }
    __syncthreads();
    if (tid == 0){
        float sl = 0.0f, st = 0.0f;
        #pragma unroll
        for (int w = 0; w < 8; w++){ sl += redL[w]; st += redT[w]; }
        g_plow[blockIdx.x] = sl;
        g_ptot[blockIdx.x] = st;
    }
}

// Kernel 3: deterministic final reduction -> scalar
__global__ void __launch_bounds__(1024) finalize_kernel(float* __restrict__ out){
    int t = threadIdx.x;
    int b = t >> 5, lane = t & 31;
    float L = 0.0f, T = 0.0f;
    for (int i = lane; i < 128; i += 32){
        L += g_plow[b * 128 + i];
        T += g_ptot[b * 128 + i];
    }
    #pragma unroll
    for (int o = 16; o; o >>= 1){
        L += __shfl_down_sync(0xffffffffu, L, o);
        T += __shfl_down_sync(0xffffffffu, T, o);
    }
    __shared__ float s[32];
    if (lane == 0) s[b] = L / T;
    __syncthreads();
    if (t < 32){
        float v = s[t];
        #pragma unroll
        for (int o = 16; o; o >>= 1) v += __shfl_down_sync(0xffffffffu, v, o);
        if (t == 0) out[0] = v * (1.0f / 32.0f);
    }
}

extern "C" void kernel_launch(void* const* d_in, const int* in_sizes, int n_in,
                              void* d_out, int out_size){
    const float* img = (const float*)d_in[0];
    float* out = (float*)d_out;
    (void)in_sizes; (void)n_in; (void)out_size;

    fft_rows_kernel<<<32 * 128, NTHR>>>(img);
    fft_cols_kernel<<<32 * 128, NTHR>>>();
    finalize_kernel<<<1, 1024>>>(out);
}

// round 3
// speedup vs baseline: 3.3392x; 3.3392x over previous
#include <cuda_runtime.h>
#include <cstdint>

// ---------------------------------------------------------------------------
// FFT mura metric, v3 (= v2 with the row-coverage launch bug fixed):
//  - rows pass: pack 2 real rows into 1 complex 512-pt FFT, Hermitian unpack,
//    store transposed scratch only for k = 0..256  (34 MB instead of 67 MB)
//    *** 512 rows = 256 pairs = 64 groups/image -> grid 32*64 (was 32*32) ***
//  - cols pass: 512-pt complex FFT per k, magnitudes, interior k weighted x2
//  - 512-pt FFT = 3x radix-8; exchange1 via shared (pitch 72), exchange2 via
//    8x8 register shuffle transpose; twiddles via __sincosf + chained cmul.
// ---------------------------------------------------------------------------

#define NTHR      256
#define REG_PITCH 580     // float2 per FFT-group region (bank-staggered)

__device__ float2 g_scratch[32u * 257u * 512u];   // [b][k=0..256][r]
__device__ float  g_plow[32 * 65];
__device__ float  g_ptot[32 * 65];

__device__ __forceinline__ float2 cadd(float2 a, float2 b){ return make_float2(a.x+b.x, a.y+b.y); }
__device__ __forceinline__ float2 csub(float2 a, float2 b){ return make_float2(a.x-b.x, a.y-b.y); }
__device__ __forceinline__ float2 cmul(float2 a, float2 b){
    return make_float2(a.x*b.x - a.y*b.y, a.x*b.y + a.y*b.x);
}
__device__ __forceinline__ float2 mnegi(float2 a){ return make_float2( a.y, -a.x); } // * (-i)
__device__ __forceinline__ float2 mposi(float2 a){ return make_float2(-a.y,  a.x); } // * (+i)

// 8-point DFT, natural order: v[m'] = sum_m v_in[m] * w8^(m*m'), w8 = e^{-i pi/4}
__device__ __forceinline__ void dft8(float2* v){
    const float C = 0.70710678118654752440f;
    float2 t0 = cadd(v[0], v[4]);
    float2 t1 = csub(v[0], v[4]);
    float2 t2 = cadd(v[2], v[6]);
    float2 t3 = csub(v[2], v[6]);
    float2 E0 = cadd(t0, t2), E2 = csub(t0, t2);
    float2 E1 = cadd(t1, mnegi(t3));
    float2 E3 = cadd(t1, mposi(t3));
    float2 s0 = cadd(v[1], v[5]);
    float2 s1 = csub(v[1], v[5]);
    float2 s2 = cadd(v[3], v[7]);
    float2 s3 = csub(v[3], v[7]);
    float2 O0 = cadd(s0, s2), O2 = csub(s0, s2);
    float2 O1 = cadd(s1, mnegi(s3));
    float2 O3 = cadd(s1, mposi(s3));
    float2 w1O1 = make_float2(C*(O1.x + O1.y), C*(O1.y - O1.x));
    float2 w2O2 = mnegi(O2);
    float2 w3O3 = make_float2(C*(O3.y - O3.x), -C*(O3.x + O3.y));
    v[0] = cadd(E0, O0);   v[4] = csub(E0, O0);
    v[1] = cadd(E1, w1O1); v[5] = csub(E1, w1O1);
    v[2] = cadd(E2, w2O2); v[6] = csub(E2, w2O2);
    v[3] = cadd(E3, w3O3); v[7] = csub(E3, w3O3);
}

__device__ __forceinline__ float2 shflx(float2 v, int d){
    v.x = __shfl_xor_sync(0xffffffffu, v.x, d);
    v.y = __shfl_xor_sync(0xffffffffu, v.y, d);
    return v;
}

// 8x8 transpose across 8 consecutive lanes (i = lane&7): out a[j] = in a_laneJ[i]
__device__ __forceinline__ void transpose8(float2 a[8], int i){
    #pragma unroll
    for (int d = 1; d < 8; d <<= 1){
        #pragma unroll
        for (int r = 0; r < 8; r++){
            if (r & d) continue;
            const int mate = r | d;
            float2 send = (i & d) ? a[r] : a[mate];
            float2 recv = shflx(send, d);
            if (i & d) a[r] = recv; else a[mate] = recv;
        }
    }
}

// Cooperative 512-pt FFT by 64 threads (n = 0..63) sharing srow.
// Input : a[m] = x[n + 64*m]
// Output: a[t1] = X[(n>>3) + 8*(n&7) + 64*t1]
// Contains one __syncthreads(); all 256 block threads must call together.
// srow is "busy" until the caller syncs after return.
__device__ __forceinline__ void fft512(float2 a[8], float2* srow, int n){
    const int mp = n >> 3, i = n & 7;

    dft8(a);
    float sn, cn;
    __sincosf((float)n * (-6.28318530717958647693f / 512.0f), &sn, &cn);
    {
        float2 base = make_float2(cn, sn);
        float2 w = base;
        #pragma unroll
        for (int m = 1; m < 8; m++){
            a[m] = cmul(a[m], w);
            if (m < 7) w = cmul(w, base);
        }
    }
    #pragma unroll
    for (int m = 0; m < 8; m++) srow[m * 72 + n] = a[m];
    __syncthreads();
    #pragma unroll
    for (int s = 0; s < 8; s++) a[s] = srow[mp * 72 + i + 8 * s];

    dft8(a);
    float s2, c2;
    __sincosf((float)i * (-6.28318530717958647693f / 64.0f), &s2, &c2);
    {
        float2 base = make_float2(c2, s2);
        float2 w = base;
        #pragma unroll
        for (int t = 1; t < 8; t++){
            a[t] = cmul(a[t], w);
            if (t < 7) w = cmul(w, base);
        }
    }
    transpose8(a, i);
    dft8(a);
}

// Kernel 1: gray + packed row FFT pairs + Hermitian unpack + transposed store
// Grid: 32 images * 64 row-groups; each block: 4 row-pairs (8 rows).
__global__ void __launch_bounds__(NTHR) fft_rows_kernel(const float* __restrict__ img){
    __shared__ float2 sbuf[4 * REG_PITCH];
    const int tid = threadIdx.x;
    const int b   = blockIdx.x >> 6;
    const int g   = blockIdx.x & 63;      // row group: rows g*8 .. g*8+7
    const int rr  = tid >> 6;             // pair index 0..3
    const int n   = tid & 63;

    const int row_e = g * 8 + rr * 2;
    const float* pe = img + (size_t)b * 786432u + (size_t)row_e * 512u;
    const float* po = pe + 512;

    float2 a[8];
    #pragma unroll
    for (int m = 0; m < 8; m++){
        int c = n + 64 * m;
        float ge = (pe[c] + pe[262144 + c] + pe[524288 + c]) * (1.0f / 3.0f);
        float go = (po[c] + po[262144 + c] + po[524288 + c]) * (1.0f / 3.0f);
        a[m] = make_float2(ge, go);       // z = even + i*odd
    }

    float2* srow = sbuf + rr * REG_PITCH;
    fft512(a, srow, n);
    __syncthreads();                       // exchange-1 loads done before restage

    // stage Z in natural k order, pad every 8 to stagger banks
    {
        const int kb = (n >> 3) + 8 * (n & 7);
        #pragma unroll
        for (int t1 = 0; t1 < 8; t1++){
            int k = kb + 64 * t1;
            srow[k + (k >> 3)] = a[t1];
        }
    }
    __syncthreads();

    // Hermitian unpack: lane = 4*kk + p ; each lane emits (Xe,Xo) for (k, pair p)
    const int w  = tid >> 5, l = tid & 31;
    const int kk = l >> 2,  p = l & 3;
    const float2* shp = sbuf + p * REG_PITCH;
    #pragma unroll
    for (int it = 0; it < 5; it++){
        int  k   = it * 64 + w * 8 + kk;
        bool act = true;
        if (it == 4){ k = 256; act = (w == 0 && kk == 0); }
        if (act){
            int km = (512 - k) & 511;
            float2 zk = shp[k  + (k  >> 3)];
            float2 zm = shp[km + (km >> 3)];
            float2 Xe = make_float2(0.5f * (zk.x + zm.x), 0.5f * (zk.y - zm.y));
            float2 Xo = make_float2(0.5f * (zk.y + zm.y), 0.5f * (zm.x - zk.x));
            size_t off = ((size_t)(b * 257 + k) << 9) + (size_t)(g * 8 + 2 * p);
            *reinterpret_cast<float4*>(&g_scratch[off]) =
                make_float4(Xe.x, Xe.y, Xo.x, Xo.y);
        }
    }
}

// Kernel 2: column FFT for k = 0..256, masked magnitude sums (interior k x2)
__global__ void __launch_bounds__(NTHR) fft_cols_kernel(void){
    __shared__ float2 sbuf[4 * REG_PITCH];
    __shared__ float redL[8], redT[8];
    const int tid = threadIdx.x;
    const int b   = blockIdx.x / 65;
    const int kg  = blockIdx.x % 65;
    const int rr  = tid >> 6;
    const int n   = tid & 63;
    const int krow  = kg * 4 + rr;
    const bool valid = (krow < 257);

    const float2* src = g_scratch + ((size_t)(b * 257 + (valid ? krow : 0)) << 9);
    float2 a[8];
    #pragma unroll
    for (int m = 0; m < 8; m++)
        a[m] = valid ? src[n + 64 * m] : make_float2(0.0f, 0.0f);

    fft512(a, sbuf + rr * REG_PITCH, n);

    // a[t1] = F[u][krow], u = (n>>3) + 8*(n&7) + 64*t1
    const int ub = (n >> 3) + 8 * (n & 7);
    float wgt = !valid ? 0.0f : ((krow == 0 || krow == 256) ? 1.0f : 2.0f);
    float dx  = (float)(krow - 256);
    float dx2 = dx * dx;
    float L = 0.0f, T = 0.0f;
    #pragma unroll
    for (int t1 = 0; t1 < 8; t1++){
        int u = ub + 64 * t1;
        float2 v = a[t1];
        float mag = sqrtf(v.x * v.x + v.y * v.y);
        T += mag;
        float dy = (float)(u - 256);
        if (dy * dy + dx2 <= 2621.44f) L += mag;   // (512*0.1)^2
    }
    L *= wgt; T *= wgt;

    #pragma unroll
    for (int o = 16; o; o >>= 1){
        L += __shfl_down_sync(0xffffffffu, L, o);
        T += __shfl_down_sync(0xffffffffu, T, o);
    }
    const int wid = tid >> 5, lane = tid & 31;
    if (lane == 0){ redL[wid] = L; redT[wid] = T; }
    __syncthreads();
    if (tid == 0){
        float sl = 0.0f, st = 0.0f;
        #pragma unroll
        for (int q = 0; q < 8; q++){ sl += redL[q]; st += redT[q]; }
        g_plow[blockIdx.x] = sl;
        g_ptot[blockIdx.x] = st;
    }
}

// Kernel 3: deterministic final reduction -> scalar
__global__ void __launch_bounds__(1024) finalize_kernel(float* __restrict__ out){
    const int t = threadIdx.x;
    const int b = t >> 5, lane = t & 31;
    float L = 0.0f, T = 0.0f;
    for (int i = lane; i < 65; i += 32){
        L += g_plow[b * 65 + i];
        T += g_ptot[b * 65 + i];
    }
    #pragma unroll
    for (int o = 16; o; o >>= 1){
        L += __shfl_down_sync(0xffffffffu, L, o);
        T += __shfl_down_sync(0xffffffffu, T, o);
    }
    __shared__ float s[32];
    if (lane == 0) s[b] = L / T;
    __syncthreads();
    if (t < 32){
        float v = s[t];
        #pragma unroll
        for (int o = 16; o; o >>= 1) v += __shfl_down_sync(0xffffffffu, v, o);
        if (t == 0) out[0] = v * (1.0f / 32.0f);
    }
}

extern "C" void kernel_launch(void* const* d_in, const int* in_sizes, int n_in,
                              void* d_out, int out_size){
    const float* img = (const float*)d_in[0];
    float* out = (float*)d_out;
    (void)in_sizes; (void)n_in; (void)out_size;

    fft_rows_kernel<<<32 * 64, NTHR>>>(img);
    fft_cols_kernel<<<32 * 65, NTHR>>>();
    finalize_kernel<<<1, 1024>>>(out);
}

// round 4
// speedup vs baseline: 3.5411x; 1.0605x over previous
#include <cuda_runtime.h>
#include <cuda_fp16.h>
#include <cstdint>

// ---------------------------------------------------------------------------
// FFT mura metric, v4:
//  - v3 structure (packed real-pair row FFTs, Hermitian half-spectrum k<=256,
//    shuffle exchange-2, computed twiddles)
//  - scratch stored as fp16 (__half2 per complex): 17 MB, fits in L2
//  - image loads use __ldcs (evict-first) so scratch stays L2-resident
//  - magnitudes via sqrt.approx (single MUFU)
// ---------------------------------------------------------------------------

#define NTHR      256
#define REG_PITCH 580     // float2 per FFT-group region (bank-staggered)

__device__ __half2 g_scratch[32u * 257u * 512u];   // [b][k=0..256][r], complex as half2
__device__ float   g_plow[32 * 65];
__device__ float   g_ptot[32 * 65];

struct alignas(8) H2X2 { __half2 e, o; };

__device__ __forceinline__ float2 cadd(float2 a, float2 b){ return make_float2(a.x+b.x, a.y+b.y); }
__device__ __forceinline__ float2 csub(float2 a, float2 b){ return make_float2(a.x-b.x, a.y-b.y); }
__device__ __forceinline__ float2 cmul(float2 a, float2 b){
    return make_float2(a.x*b.x - a.y*b.y, a.x*b.y + a.y*b.x);
}
__device__ __forceinline__ float2 mnegi(float2 a){ return make_float2( a.y, -a.x); } // * (-i)
__device__ __forceinline__ float2 mposi(float2 a){ return make_float2(-a.y,  a.x); } // * (+i)

__device__ __forceinline__ float fsqrt_approx(float x){
    float r; asm("sqrt.approx.f32 %0, %1;" : "=f"(r) : "f"(x)); return r;
}

// 8-point DFT, natural order: v[m'] = sum_m v_in[m] * w8^(m*m'), w8 = e^{-i pi/4}
__device__ __forceinline__ void dft8(float2* v){
    const float C = 0.70710678118654752440f;
    float2 t0 = cadd(v[0], v[4]);
    float2 t1 = csub(v[0], v[4]);
    float2 t2 = cadd(v[2], v[6]);
    float2 t3 = csub(v[2], v[6]);
    float2 E0 = cadd(t0, t2), E2 = csub(t0, t2);
    float2 E1 = cadd(t1, mnegi(t3));
    float2 E3 = cadd(t1, mposi(t3));
    float2 s0 = cadd(v[1], v[5]);
    float2 s1 = csub(v[1], v[5]);
    float2 s2 = cadd(v[3], v[7]);
    float2 s3 = csub(v[3], v[7]);
    float2 O0 = cadd(s0, s2), O2 = csub(s0, s2);
    float2 O1 = cadd(s1, mnegi(s3));
    float2 O3 = cadd(s1, mposi(s3));
    float2 w1O1 = make_float2(C*(O1.x + O1.y), C*(O1.y - O1.x));
    float2 w2O2 = mnegi(O2);
    float2 w3O3 = make_float2(C*(O3.y - O3.x), -C*(O3.x + O3.y));
    v[0] = cadd(E0, O0);   v[4] = csub(E0, O0);
    v[1] = cadd(E1, w1O1); v[5] = csub(E1, w1O1);
    v[2] = cadd(E2, w2O2); v[6] = csub(E2, w2O2);
    v[3] = cadd(E3, w3O3); v[7] = csub(E3, w3O3);
}

__device__ __forceinline__ float2 shflx(float2 v, int d){
    v.x = __shfl_xor_sync(0xffffffffu, v.x, d);
    v.y = __shfl_xor_sync(0xffffffffu, v.y, d);
    return v;
}

// 8x8 transpose across 8 consecutive lanes (i = lane&7): out a[j] = in a_laneJ[i]
__device__ __forceinline__ void transpose8(float2 a[8], int i){
    #pragma unroll
    for (int d = 1; d < 8; d <<= 1){
        #pragma unroll
        for (int r = 0; r < 8; r++){
            if (r & d) continue;
            const int mate = r | d;
            float2 send = (i & d) ? a[r] : a[mate];
            float2 recv = shflx(send, d);
            if (i & d) a[r] = recv; else a[mate] = recv;
        }
    }
}

// Cooperative 512-pt FFT by 64 threads (n = 0..63) sharing srow.
// Input : a[m] = x[n + 64*m]
// Output: a[t1] = X[(n>>3) + 8*(n&7) + 64*t1]
// Contains one __syncthreads(); all 256 block threads must call together.
// srow is "busy" until the caller syncs after return.
__device__ __forceinline__ void fft512(float2 a[8], float2* srow, int n){
    const int mp = n >> 3, i = n & 7;

    dft8(a);
    float sn, cn;
    __sincosf((float)n * (-6.28318530717958647693f / 512.0f), &sn, &cn);
    {
        float2 base = make_float2(cn, sn);
        float2 w = base;
        #pragma unroll
        for (int m = 1; m < 8; m++){
            a[m] = cmul(a[m], w);
            if (m < 7) w = cmul(w, base);
        }
    }
    #pragma unroll
    for (int m = 0; m < 8; m++) srow[m * 72 + n] = a[m];
    __syncthreads();
    #pragma unroll
    for (int s = 0; s < 8; s++) a[s] = srow[mp * 72 + i + 8 * s];

    dft8(a);
    float s2, c2;
    __sincosf((float)i * (-6.28318530717958647693f / 64.0f), &s2, &c2);
    {
        float2 base = make_float2(c2, s2);
        float2 w = base;
        #pragma unroll
        for (int t = 1; t < 8; t++){
            a[t] = cmul(a[t], w);
            if (t < 7) w = cmul(w, base);
        }
    }
    transpose8(a, i);
    dft8(a);
}

// Kernel 1: gray + packed row FFT pairs + Hermitian unpack + fp16 transposed store
// Grid: 32 images * 64 row-groups; each block: 4 row-pairs (8 rows).
__global__ void __launch_bounds__(NTHR) fft_rows_kernel(const float* __restrict__ img){
    __shared__ float2 sbuf[4 * REG_PITCH];
    const int tid = threadIdx.x;
    const int b   = blockIdx.x >> 6;
    const int g   = blockIdx.x & 63;      // row group: rows g*8 .. g*8+7
    const int rr  = tid >> 6;             // pair index 0..3
    const int n   = tid & 63;

    const int row_e = g * 8 + rr * 2;
    const float* pe = img + (size_t)b * 786432u + (size_t)row_e * 512u;
    const float* po = pe + 512;

    float2 a[8];
    #pragma unroll
    for (int m = 0; m < 8; m++){
        int c = n + 64 * m;
        float ge = (__ldcs(pe + c) + __ldcs(pe + 262144 + c) + __ldcs(pe + 524288 + c)) * (1.0f / 3.0f);
        float go = (__ldcs(po + c) + __ldcs(po + 262144 + c) + __ldcs(po + 524288 + c)) * (1.0f / 3.0f);
        a[m] = make_float2(ge, go);       // z = even + i*odd
    }

    float2* srow = sbuf + rr * REG_PITCH;
    fft512(a, srow, n);
    __syncthreads();                       // exchange-1 loads done before restage

    // stage Z in natural k order, pad every 8 to stagger banks
    {
        const int kb = (n >> 3) + 8 * (n & 7);
        #pragma unroll
        for (int t1 = 0; t1 < 8; t1++){
            int k = kb + 64 * t1;
            srow[k + (k >> 3)] = a[t1];
        }
    }
    __syncthreads();

    // Hermitian unpack: lane = 4*kk + p ; each lane emits (Xe,Xo) for (k, pair p)
    const int w  = tid >> 5, l = tid & 31;
    const int kk = l >> 2,  p = l & 3;
    const float2* shp = sbuf + p * REG_PITCH;
    #pragma unroll
    for (int it = 0; it < 5; it++){
        int  k   = it * 64 + w * 8 + kk;
        bool act = true;
        if (it == 4){ k = 256; act = (w == 0 && kk == 0); }
        if (act){
            int km = (512 - k) & 511;
            float2 zk = shp[k  + (k  >> 3)];
            float2 zm = shp[km + (km >> 3)];
            float2 Xe = make_float2(0.5f * (zk.x + zm.x), 0.5f * (zk.y - zm.y));
            float2 Xo = make_float2(0.5f * (zk.y + zm.y), 0.5f * (zm.x - zk.x));
            size_t off = ((size_t)(b * 257 + k) << 9) + (size_t)(g * 8 + 2 * p);
            H2X2 val;
            val.e = __float22half2_rn(Xe);
            val.o = __float22half2_rn(Xo);
            *reinterpret_cast<H2X2*>(&g_scratch[off]) = val;
        }
    }
}

// Kernel 2: column FFT for k = 0..256, masked magnitude sums (interior k x2)
__global__ void __launch_bounds__(NTHR) fft_cols_kernel(void){
    __shared__ float2 sbuf[4 * REG_PITCH];
    __shared__ float redL[8], redT[8];
    const int tid = threadIdx.x;
    const int b   = blockIdx.x / 65;
    const int kg  = blockIdx.x % 65;
    const int rr  = tid >> 6;
    const int n   = tid & 63;
    const int krow  = kg * 4 + rr;
    const bool valid = (krow < 257);

    const __half2* src = g_scratch + ((size_t)(b * 257 + (valid ? krow : 0)) << 9);
    float2 a[8];
    #pragma unroll
    for (int m = 0; m < 8; m++){
        __half2 h = __ldcs(src + n + 64 * m);
        float2 v = __half22float2(h);
        a[m] = valid ? v : make_float2(0.0f, 0.0f);
    }

    fft512(a, sbuf + rr * REG_PITCH, n);

    // a[t1] = F[u][krow], u = (n>>3) + 8*(n&7) + 64*t1
    const int ub = (n >> 3) + 8 * (n & 7);
    float wgt = !valid ? 0.0f : ((krow == 0 || krow == 256) ? 1.0f : 2.0f);
    float dx  = (float)(krow - 256);
    float dx2 = dx * dx;
    float L = 0.0f, T = 0.0f;
    #pragma unroll
    for (int t1 = 0; t1 < 8; t1++){
        int u = ub + 64 * t1;
        float2 v = a[t1];
        float mag = fsqrt_approx(v.x * v.x + v.y * v.y);
        T += mag;
        float dy = (float)(u - 256);
        if (dy * dy + dx2 <= 2621.44f) L += mag;   // (512*0.1)^2
    }
    L *= wgt; T *= wgt;

    #pragma unroll
    for (int o = 16; o; o >>= 1){
        L += __shfl_down_sync(0xffffffffu, L, o);
        T += __shfl_down_sync(0xffffffffu, T, o);
    }
    const int wid = tid >> 5, lane = tid & 31;
    if (lane == 0){ redL[wid] = L; redT[wid] = T; }
    __syncthreads();
    if (tid == 0){
        float sl = 0.0f, st = 0.0f;
        #pragma unroll
        for (int q = 0; q < 8; q++){ sl += redL[q]; st += redT[q]; }
        g_plow[blockIdx.x] = sl;
        g_ptot[blockIdx.x] = st;
    }
}

// Kernel 3: deterministic final reduction -> scalar
__global__ void __launch_bounds__(1024) finalize_kernel(float* __restrict__ out){
    const int t = threadIdx.x;
    const int b = t >> 5, lane = t & 31;
    float L = 0.0f, T = 0.0f;
    for (int i = lane; i < 65; i += 32){
        L += g_plow[b * 65 + i];
        T += g_ptot[b * 65 + i];
    }
    #pragma unroll
    for (int o = 16; o; o >>= 1){
        L += __shfl_down_sync(0xffffffffu, L, o);
        T += __shfl_down_sync(0xffffffffu, T, o);
    }
    __shared__ float s[32];
    if (lane == 0) s[b] = L / T;
    __syncthreads();
    if (t < 32){
        float v = s[t];
        #pragma unroll
        for (int o = 16; o; o >>= 1) v += __shfl_down_sync(0xffffffffu, v, o);
        if (t == 0) out[0] = v * (1.0f / 32.0f);
    }
}

extern "C" void kernel_launch(void* const* d_in, const int* in_sizes, int n_in,
                              void* d_out, int out_size){
    const float* img = (const float*)d_in[0];
    float* out = (float*)d_out;
    (void)in_sizes; (void)n_in; (void)out_size;

    fft_rows_kernel<<<32 * 64, NTHR>>>(img);
    fft_cols_kernel<<<32 * 65, NTHR>>>();
    finalize_kernel<<<1, 1024>>>(out);
}